// round 2
// baseline (speedup 1.0000x reference)
#include <cuda_runtime.h>
#include <cstdint>
#include <cstddef>

// ---------------- problem constants ----------------
#define QL 1024
#define MLEN 1024
#define KL 2048
#define DMODEL 256
#define NH 8
#define DH 32
#define FF 1024
#define G3 768   // 3*DMODEL

// ---------------- scratch (floats) ----------------
#define N_CAT   (KL*DMODEL)
#define N_QKV   (KL*G3)
#define N_RH    (KL*DMODEL)
#define N_QU    (NH*QL*DH)
#define N_KB    (NH*KL*DH)
#define N_SC    ((size_t)NH*QL*KL)
#define N_ROW   (QL*DMODEL)
#define N_GI    (QL*G3)
#define N_MLPH  (QL*FF)

__device__ __align__(16) float g_scr[
    N_CAT + N_QKV + N_RH + 2*N_QU + 3*N_KB +
    3*N_SC +
    5*N_ROW + N_GI + 2*N_ROW + N_MLPH + 2*N_ROW + N_GI
];

#define OFF_CAT  ((size_t)0)
#define OFF_QKV  (OFF_CAT + N_CAT)
#define OFF_RH   (OFF_QKV + N_QKV)
#define OFF_QU   (OFF_RH  + N_RH)
#define OFF_QV   (OFF_QU  + N_QU)
#define OFF_KB   (OFF_QV  + N_QU)
#define OFF_RB   (OFF_KB  + N_KB)
#define OFF_VT   (OFF_RB  + N_KB)
#define OFF_AC   (OFF_VT  + N_KB)
#define OFF_BD   (OFF_AC  + N_SC)
#define OFF_P    (OFF_BD  + N_SC)
#define OFF_AV   (OFF_P   + N_SC)
#define OFF_Y    (OFF_AV  + N_ROW)
#define OFF_LN   (OFF_Y   + N_ROW)
#define OFF_GIN  (OFF_LN  + N_ROW)
#define OFF_GI   (OFF_GIN + N_ROW)
#define OFF_YS1  (OFF_GI  + N_GI)
#define OFF_LN2  (OFF_YS1 + N_ROW)
#define OFF_MLPH (OFF_LN2 + N_ROW)
#define OFF_MLPO (OFF_MLPH + N_MLPH)
#define OFF_GIN2 (OFF_MLPO + N_ROW)
#define OFF_GI2  (OFF_GIN2 + N_ROW)

// ---------------- fp32 SGEMM: C = A(MxK) * B(NxK)^T (+bias)(+relu), batched ----------------
#define BM 64
#define BN 64
#define BKT 16

__global__ void __launch_bounds__(256)
k_sgemm(const float* __restrict__ A, const float* __restrict__ B,
        const float* __restrict__ bias, float* __restrict__ C,
        int M, int N, int K, int lda, int ldb, int ldc,
        size_t sA, size_t sB, size_t sC, int relu)
{
    int bz = blockIdx.z;
    A += (size_t)bz * sA;  B += (size_t)bz * sB;  C += (size_t)bz * sC;

    __shared__ float As[BKT][BM];
    __shared__ float Bs[BKT][BN];

    int tid = threadIdx.x;
    int row0 = blockIdx.y * BM, col0 = blockIdx.x * BN;
    int tx = tid & 15, ty = tid >> 4;
    int ar = tid >> 2;           // 0..63
    int ak = (tid & 3) * 4;      // 0,4,8,12

    float acc[4][4];
#pragma unroll
    for (int i = 0; i < 4; i++)
#pragma unroll
        for (int j = 0; j < 4; j++) acc[i][j] = 0.f;

    for (int k0 = 0; k0 < K; k0 += BKT) {
        float4 a4 = make_float4(0.f,0.f,0.f,0.f);
        float4 b4 = make_float4(0.f,0.f,0.f,0.f);
        int gr = row0 + ar, gk = k0 + ak, gc = col0 + ar;
        if (gr < M && gk < K) a4 = *(const float4*)(A + (size_t)gr * lda + gk);
        if (gc < N && gk < K) b4 = *(const float4*)(B + (size_t)gc * ldb + gk);
        As[ak+0][ar]=a4.x; As[ak+1][ar]=a4.y; As[ak+2][ar]=a4.z; As[ak+3][ar]=a4.w;
        Bs[ak+0][ar]=b4.x; Bs[ak+1][ar]=b4.y; Bs[ak+2][ar]=b4.z; Bs[ak+3][ar]=b4.w;
        __syncthreads();
#pragma unroll
        for (int kk = 0; kk < BKT; kk++) {
            float4 av4 = *(const float4*)&As[kk][ty*4];
            float4 bv4 = *(const float4*)&Bs[kk][tx*4];
            float a[4] = {av4.x, av4.y, av4.z, av4.w};
            float b[4] = {bv4.x, bv4.y, bv4.z, bv4.w};
#pragma unroll
            for (int i = 0; i < 4; i++)
#pragma unroll
                for (int j = 0; j < 4; j++)
                    acc[i][j] = fmaf(a[i], b[j], acc[i][j]);
        }
        __syncthreads();
    }

#pragma unroll
    for (int i = 0; i < 4; i++) {
        int r = row0 + ty*4 + i;
        if (r >= M) continue;
#pragma unroll
        for (int j = 0; j < 4; j++) {
            int c = col0 + tx*4 + j;
            if (c >= N) continue;
            float v = acc[i][j];
            if (bias) v += bias[c];
            if (relu) v = v > 0.f ? v : 0.f;
            C[(size_t)r * ldc + c] = v;
        }
    }
}

// ---------------- small kernels ----------------
__global__ void k_concat(const float* __restrict__ mem, const float* __restrict__ inp,
                         float* __restrict__ cat)
{
    int idx = blockIdx.x * blockDim.x + threadIdx.x;
    int row = idx >> 8;
    cat[idx] = (row < MLEN) ? mem[idx] : inp[idx - MLEN * DMODEL];
}

__global__ void k_prep_q(const float* __restrict__ qkv, const float* __restrict__ u,
                         const float* __restrict__ v, float* __restrict__ qu,
                         float* __restrict__ qv)
{
    int idx = blockIdx.x * blockDim.x + threadIdx.x;   // h*QL*DH + i*DH + d
    int h = idx >> 15;
    int rem = idx & 32767;
    int i = rem >> 5, d = rem & 31;
    int c = (h << 5) + d;
    float val = qkv[(size_t)(MLEN + i) * G3 + c];
    qu[idx] = val + u[c];
    qv[idx] = val + v[c];
}

__global__ void k_prep_kv(const float* __restrict__ qkv, const float* __restrict__ rh,
                          float* __restrict__ kb, float* __restrict__ rb,
                          float* __restrict__ vt)
{
    int idx = blockIdx.x * blockDim.x + threadIdx.x;   // h*KL*DH + j*DH + d
    int h = idx >> 16;
    int rem = idx & 65535;
    int j = rem >> 5, d = rem & 31;
    int c = (h << 5) + d;
    kb[idx] = qkv[(size_t)j * G3 + DMODEL + c];
    rb[idx] = rh[(size_t)j * DMODEL + c];
    vt[((size_t)h << 16) + ((size_t)d << 11) + j] = qkv[(size_t)j * G3 + 2*DMODEL + c];
}

__global__ void k_add(const float* __restrict__ a, const float* __restrict__ b,
                      float* __restrict__ c)
{
    int idx = blockIdx.x * blockDim.x + threadIdx.x;
    c[idx] = a[idx] + b[idx];
}

__global__ void k_ln(const float* __restrict__ in, const float* __restrict__ g,
                     const float* __restrict__ b, float* __restrict__ out)
{
    __shared__ float red[256];
    int row = blockIdx.x, tid = threadIdx.x;
    float x = in[(size_t)row * DMODEL + tid];
    red[tid] = x; __syncthreads();
    for (int s = 128; s > 0; s >>= 1) { if (tid < s) red[tid] += red[tid + s]; __syncthreads(); }
    float mu = red[0] * (1.f / DMODEL);
    __syncthreads();
    float dx = x - mu;
    red[tid] = dx * dx; __syncthreads();
    for (int s = 128; s > 0; s >>= 1) { if (tid < s) red[tid] += red[tid + s]; __syncthreads(); }
    float var = red[0] * (1.f / DMODEL);
    out[(size_t)row * DMODEL + tid] = dx * rsqrtf(var + 1e-5f) * g[tid] + b[tid];
}

// softmax with analytic rel-shift + causal(mem) mask; block = (i, h)
__global__ void __launch_bounds__(256) k_softmax(const float* __restrict__ AC,
                                                 const float* __restrict__ BD,
                                                 float* __restrict__ P)
{
    __shared__ float sb[KL];
    __shared__ float red[256];
    int i = blockIdx.x, h = blockIdx.y, tid = threadIdx.x;
    const float* ac = AC + ((size_t)h << 21) + ((size_t)i << 11);
    const float* bd = BD + ((size_t)h << 21) + ((size_t)i << 11) + (QL - 1 - i);
    float* p = P + ((size_t)h << 21) + ((size_t)i << 11);
    int lim = i + MLEN;
    const float scale = 0.17677669529663687f; // 1/sqrt(32)

    float mx = -1e30f;
    for (int j = tid; j < KL; j += 256) {
        float s = (j <= lim) ? (ac[j] + bd[j]) * scale : -1e30f;
        sb[j] = s;
        mx = fmaxf(mx, s);
    }
    red[tid] = mx; __syncthreads();
    for (int s = 128; s > 0; s >>= 1) { if (tid < s) red[tid] = fmaxf(red[tid], red[tid+s]); __syncthreads(); }
    float mxv = red[0];
    __syncthreads();

    float sum = 0.f;
    for (int j = tid; j < KL; j += 256) {
        float e = expf(sb[j] - mxv);
        sb[j] = e;
        sum += e;
    }
    red[tid] = sum; __syncthreads();
    for (int s = 128; s > 0; s >>= 1) { if (tid < s) red[tid] += red[tid+s]; __syncthreads(); }
    float inv = 1.f / red[0];
    __syncthreads();

    for (int j = tid; j < KL; j += 256) p[j] = sb[j] * inv;
}

// attn(i,j,h) output from P(h,i,j)
__global__ void k_inter(const float* __restrict__ P, float* __restrict__ attn)
{
    int idx = blockIdx.x * blockDim.x + threadIdx.x;   // i*2048 + j
    float v[8];
#pragma unroll
    for (int h = 0; h < 8; h++) v[h] = P[((size_t)h << 21) + idx];
    float4* o = (float4*)(attn + (size_t)idx * 8);
    o[0] = make_float4(v[0], v[1], v[2], v[3]);
    o[1] = make_float4(v[4], v[5], v[6], v[7]);
}

// ---------------- GRU scan: 8-CTA cluster, register-resident Whh ----------------
__global__ void __launch_bounds__(192, 1) __cluster_dims__(8, 1, 1)
k_gru(const float* __restrict__ gi, const float* __restrict__ Whh,
      const float* __restrict__ bhh, float* __restrict__ ys)
{
    __shared__ float hbuf[512];   // double-buffered h (2 x 256)
    __shared__ float ghb[96];

    int tid = threadIdx.x;
    unsigned rank;
    asm("mov.u32 %0, %%cluster_ctarank;" : "=r"(rank));

    // thread = (row rr = tid>>1, hlf = tid&1); row rr handles gate=rr/32, dim dl=rr%32
    int rr = tid >> 1, hlf = tid & 1;
    int gate = rr >> 5, dl = rr & 31;
    int grow = gate * 256 + (int)rank * 32 + dl;
    const float4* wp = (const float4*)(Whh + (size_t)grow * DMODEL + hlf * 128);
    float4 w[32];
#pragma unroll
    for (int q = 0; q < 32; q++) w[q] = __ldg(&wp[q]);

    for (int i2 = tid; i2 < 512; i2 += 192) hbuf[i2] = 0.f;

    float bR = 0.f, bZ = 0.f, bN = 0.f;
    int gdim = 0;
    uint32_t hb_r[8];
    if (tid < 32) {
        gdim = (int)rank * 32 + tid;
        bR = bhh[gdim]; bZ = bhh[256 + gdim]; bN = bhh[512 + gdim];
        uint32_t hb_l = (uint32_t)__cvta_generic_to_shared((void*)hbuf);
#pragma unroll
        for (int p = 0; p < 8; p++) {
            asm("mapa.shared::cluster.u32 %0, %1, %2;" : "=r"(hb_r[p]) : "r"(hb_l), "r"(p));
        }
    }
    __syncthreads();
    asm volatile("barrier.cluster.arrive.aligned;" ::: "memory");
    asm volatile("barrier.cluster.wait.aligned;" ::: "memory");

#pragma unroll 1
    for (int t = 0; t < QL; t++) {
        float ir = 0.f, iz = 0.f, inn = 0.f;
        if (tid < 32) {
            const float* g = gi + (size_t)t * G3;
            ir  = __ldg(g + gdim);
            iz  = __ldg(g + 256 + gdim);
            inn = __ldg(g + 512 + gdim);
        }
        const float4* h4 = (const float4*)(hbuf + (t & 1) * 256) + hlf * 32;
        float s0 = 0.f, s1 = 0.f, s2 = 0.f, s3 = 0.f;
#pragma unroll
        for (int q = 0; q < 32; q++) {
            float4 hv = h4[q];
            s0 = fmaf(w[q].x, hv.x, s0);
            s1 = fmaf(w[q].y, hv.y, s1);
            s2 = fmaf(w[q].z, hv.z, s2);
            s3 = fmaf(w[q].w, hv.w, s3);
        }
        float sum = (s0 + s1) + (s2 + s3);
        sum += __shfl_down_sync(0xffffffffu, sum, 1);
        if (!hlf) ghb[rr] = sum;
        __syncthreads();

        if (tid < 32) {
            float hr = ghb[tid]      + bR;
            float hz = ghb[32 + tid] + bZ;
            float hn = ghb[64 + tid] + bN;
            float rg = 1.f / (1.f + expf(-(ir + hr)));
            float zg = 1.f / (1.f + expf(-(iz + hz)));
            float ng = tanhf(inn + rg * hn);
            float hprev = hbuf[(t & 1) * 256 + gdim];
            float hnew = (1.f - zg) * ng + zg * hprev;
            ys[(size_t)t * DMODEL + gdim] = hnew;
            uint32_t off = (uint32_t)(((t + 1) & 1) * 256 + gdim) * 4u;
#pragma unroll
            for (int p = 0; p < 8; p++) {
                asm volatile("st.shared::cluster.f32 [%0], %1;"
                             :: "r"(hb_r[p] + off), "f"(hnew) : "memory");
            }
        }
        asm volatile("barrier.cluster.arrive.aligned;" ::: "memory");
        asm volatile("barrier.cluster.wait.aligned;" ::: "memory");
    }
}

// ---------------- host orchestration ----------------
static inline float* SCR(size_t off) {
    // resolved at launch time on device pointers via symbol? No: we need the
    // device address. Use a device-symbol lookup once is not allowed per-call
    // statefulness; cudaGetSymbolAddress is fine (no alloc) and deterministic.
    return nullptr; // placeholder, not used
}

extern "C" void kernel_launch(void* const* d_in, const int* in_sizes, int n_in,
                              void* d_out, int out_size) {
    const float* inputs = (const float*)d_in[0];
    const float* r      = (const float*)d_in[1];
    const float* u      = (const float*)d_in[2];
    const float* v      = (const float*)d_in[3];
    const float* mem    = (const float*)d_in[4];
    const float* ln1_g  = (const float*)d_in[5];
    const float* ln1_b  = (const float*)d_in[6];
    const float* ln2_g  = (const float*)d_in[7];
    const float* ln2_b  = (const float*)d_in[8];
    const float* Wqkv   = (const float*)d_in[9];
    const float* bqkv   = (const float*)d_in[10];
    const float* Wr     = (const float*)d_in[11];
    const float* Wo     = (const float*)d_in[12];
    const float* bo     = (const float*)d_in[13];
    const float* g1_Wih = (const float*)d_in[14];
    const float* g1_Whh = (const float*)d_in[15];
    const float* g1_bih = (const float*)d_in[16];
    const float* g1_bhh = (const float*)d_in[17];
    const float* g2_Wih = (const float*)d_in[18];
    const float* g2_Whh = (const float*)d_in[19];
    const float* g2_bih = (const float*)d_in[20];
    const float* g2_bhh = (const float*)d_in[21];
    const float* W1     = (const float*)d_in[22];
    const float* b1     = (const float*)d_in[23];
    const float* W2     = (const float*)d_in[24];
    const float* b2     = (const float*)d_in[25];

    float* scr = nullptr;
    cudaGetSymbolAddress((void**)&scr, g_scr);

    float* CAT  = scr + OFF_CAT;
    float* QKV  = scr + OFF_QKV;
    float* RH   = scr + OFF_RH;
    float* QU   = scr + OFF_QU;
    float* QV   = scr + OFF_QV;
    float* KB   = scr + OFF_KB;
    float* RB   = scr + OFF_RB;
    float* VT   = scr + OFF_VT;
    float* AC   = scr + OFF_AC;
    float* BD   = scr + OFF_BD;
    float* P    = scr + OFF_P;
    float* AV   = scr + OFF_AV;
    float* Y    = scr + OFF_Y;
    float* LN   = scr + OFF_LN;
    float* GIN  = scr + OFF_GIN;
    float* GI   = scr + OFF_GI;
    float* YS1  = scr + OFF_YS1;
    float* LN2  = scr + OFF_LN2;
    float* MLPH = scr + OFF_MLPH;
    float* MLPO = scr + OFF_MLPO;
    float* GIN2 = scr + OFF_GIN2;
    float* GI2  = scr + OFF_GI2;

    float* out_y    = (float*)d_out;
    float* out_attn = (float*)d_out + (size_t)QL * DMODEL;

    // 1. concat mem + inputs
    k_concat<<<(KL*DMODEL)/256, 256>>>(mem, inputs, CAT);
    // 2. qkv = cat @ Wqkv^T + bqkv
    k_sgemm<<<dim3(G3/BN, KL/BM, 1), 256>>>(CAT, Wqkv, bqkv, QKV,
        KL, G3, DMODEL, DMODEL, DMODEL, G3, 0, 0, 0, 0);
    // 3. rh = r @ Wr^T
    k_sgemm<<<dim3(DMODEL/BN, KL/BM, 1), 256>>>(r, Wr, nullptr, RH,
        KL, DMODEL, DMODEL, DMODEL, DMODEL, DMODEL, 0, 0, 0, 0);
    // 4/5. head-major Q(+u/+v), K, R, V^T
    k_prep_q<<<(NH*QL*DH)/256, 256>>>(QKV, u, v, QU, QV);
    k_prep_kv<<<(NH*KL*DH)/256, 256>>>(QKV, RH, KB, RB, VT);
    // 6. AC[h] = QU_h @ KB_h^T  (batched over heads)
    k_sgemm<<<dim3(KL/BN, QL/BM, NH), 256>>>(QU, KB, nullptr, AC,
        QL, KL, DH, DH, DH, KL,
        (size_t)QL*DH, (size_t)KL*DH, (size_t)QL*KL, 0);
    // 7. BDraw[h] = QV_h @ RB_h^T
    k_sgemm<<<dim3(KL/BN, QL/BM, NH), 256>>>(QV, RB, nullptr, BD,
        QL, KL, DH, DH, DH, KL,
        (size_t)QL*DH, (size_t)KL*DH, (size_t)QL*KL, 0);
    // 8. softmax with rel-shift + mask
    k_softmax<<<dim3(QL, NH), 256>>>(AC, BD, P);
    // 9. attn output (i,j,h)
    k_inter<<<(QL*KL)/256, 256>>>(P, out_attn);
    // 10. AV[h] = P_h @ VT_h^T -> av (qlen, 256)
    k_sgemm<<<dim3(1, QL/BM, NH), 256>>>(P, VT, nullptr, AV,
        QL, DH, KL, KL, KL, DMODEL,
        (size_t)QL*KL, (size_t)DH*KL, (size_t)DH, 0);
    // 11. y = av @ Wo^T + bo
    k_sgemm<<<dim3(DMODEL/BN, QL/BM, 1), 256>>>(AV, Wo, bo, Y,
        QL, DMODEL, DMODEL, DMODEL, DMODEL, DMODEL, 0, 0, 0, 0);
    // 12. ln1
    k_ln<<<QL, 256>>>(Y, ln1_g, ln1_b, LN);
    // 13. gin = inputs + ln1(y)
    k_add<<<(QL*DMODEL)/256, 256>>>(inputs, LN, GIN);
    // 14. gi1 = gin @ g1_Wih^T + g1_bih
    k_sgemm<<<dim3(G3/BN, QL/BM, 1), 256>>>(GIN, g1_Wih, g1_bih, GI,
        QL, G3, DMODEL, DMODEL, DMODEL, G3, 0, 0, 0, 0);
    // 15. GRU 1
    k_gru<<<8, 192>>>(GI, g1_Whh, g1_bhh, YS1);
    // 16. ln2
    k_ln<<<QL, 256>>>(YS1, ln2_g, ln2_b, LN2);
    // 17. mlp hidden = relu(ln2 @ W1^T + b1)
    k_sgemm<<<dim3(FF/BN, QL/BM, 1), 256>>>(LN2, W1, b1, MLPH,
        QL, FF, DMODEL, DMODEL, DMODEL, FF, 0, 0, 0, 1);
    // 18. mlp out = hidden @ W2^T + b2
    k_sgemm<<<dim3(DMODEL/BN, QL/BM, 1), 256>>>(MLPH, W2, b2, MLPO,
        QL, DMODEL, FF, FF, FF, DMODEL, 0, 0, 0, 0);
    // 19. gin2 = ys1 + mlp
    k_add<<<(QL*DMODEL)/256, 256>>>(YS1, MLPO, GIN2);
    // 20. gi2
    k_sgemm<<<dim3(G3/BN, QL/BM, 1), 256>>>(GIN2, g2_Wih, g2_bih, GI2,
        QL, G3, DMODEL, DMODEL, DMODEL, G3, 0, 0, 0, 0);
    // 21. GRU 2 -> y output
    k_gru<<<8, 192>>>(GI2, g2_Whh, g2_bhh, out_y);
}